// round 5
// baseline (speedup 1.0000x reference)
#include <cuda_runtime.h>
#include <math.h>

// Problem constants
#define BB 32
#define DD 512
#define KB 512            // codebook size
#define LLAT 1024         // latent positions per image (32*32)
#define NTOT (BB * LLAT)  // 32768 rows

// d_out layout: [recon (32*3*128*128)] [z_e (32*512*1024)] [emb (32*512*1024)]
#define RECON_ELEMS (32 * 3 * 128 * 128)
#define ZE_ELEMS (BB * DD * LLAT)

// Scratch (device globals: allocation-free)
__device__ float g_zq[(size_t)NTOT * DD];  // z_q in NCHW layout (b,d,p)
__device__ int g_idx[NTOT];
__device__ float g_w2[KB];
__device__ float g_wdt[DD * 48];  // decoder weights, flipped, [d][c*16+i*4+j]

typedef unsigned long long ull;

// Packed fp32x2 FMA: d = a*b + c elementwise on two fp32 lanes in a 64-bit reg.
// Bit-identical to two scalar fmaf's (IEEE fp32, RN).
__device__ __forceinline__ ull ffma2(ull a, ull b, ull c) {
    ull d;
    asm("fma.rn.f32x2 %0, %1, %2, %3;" : "=l"(d) : "l"(a), "l"(b), "l"(c));
    return d;
}
__device__ __forceinline__ ull pack2(float lo, float hi) {
    ull d;
    asm("mov.b64 %0, {%1, %2};" : "=l"(d) : "f"(lo), "f"(hi));
    return d;
}
__device__ __forceinline__ void unpack2(ull v, float& lo, float& hi) {
    asm("mov.b64 {%0, %1}, %2;" : "=f"(lo), "=f"(hi) : "l"(v));
}

// ---------------------------------------------------------------------------
// Prep: codebook column norms
__global__ void k_prep_w2(const float* __restrict__ cb) {
    int k = threadIdx.x;  // 512 threads
    float s = 0.f;
    for (int d = 0; d < DD; d++) {
        float v = cb[d * KB + k];
        s += v * v;
    }
    g_w2[k] = s;
}

// Prep: decoder weight transpose WITH spatial flip.
// jax conv_transpose (transpose_kernel=False, VALID, k=s=4):
//   out[b,c,4h+i,4w+j] = sum_d zq[b,d,h,w] * Wd[c,d,3-i,3-j] + bd[c]
__global__ void k_prep_wdt(const float* __restrict__ Wd) {
    int t = blockIdx.x * 256 + threadIdx.x;  // 24576 total
    int d = t / 48, m = t % 48;
    int c = m >> 4, ij = m & 15;
    int i = ij >> 2, j = ij & 3;
    g_wdt[t] = Wd[c * (DD * 16) + d * 16 + (3 - i) * 4 + (3 - j)];
}

// ---------------------------------------------------------------------------
// Encoder: z_e[b,d,p] = relu( sum_{c,i,j} x[b,c,4h+i,4w+j]*We[d,c,i,j] + be[d] )
// Patch pre-packed into f32x2 pairs; weights read as 64-bit pairs from smem.
__global__ void k_encoder(const float* __restrict__ x, const float* __restrict__ We,
                          const float* __restrict__ be, float* __restrict__ ze) {
    __shared__ float sW[128 * 48];  // 24 KB
    __shared__ float sB[DD];
    const int tid = threadIdx.x;  // 128
    const int blk = blockIdx.x;   // 256 blocks
    const int b = blk >> 3;
    const int p = ((blk & 7) << 7) + tid;  // 0..1023
    const int h = p >> 5, w = p & 31;

    for (int i = tid; i < DD; i += 128) sB[i] = be[i];

    float patch[48];
    const float* xb = x + (size_t)b * (3 * 128 * 128);
#pragma unroll
    for (int c = 0; c < 3; c++)
#pragma unroll
        for (int i = 0; i < 4; i++) {
            float4 v = *(const float4*)(xb + c * 16384 + (4 * h + i) * 128 + 4 * w);
            patch[c * 16 + i * 4 + 0] = v.x;
            patch[c * 16 + i * 4 + 1] = v.y;
            patch[c * 16 + i * 4 + 2] = v.z;
            patch[c * 16 + i * 4 + 3] = v.w;
        }
    ull ep[24];
#pragma unroll
    for (int k = 0; k < 24; k++) ep[k] = pack2(patch[2 * k], patch[2 * k + 1]);

    float* zb = ze + (size_t)b * (DD * LLAT) + p;
    const float4* We4 = (const float4*)We;
    for (int dt = 0; dt < 4; dt++) {
        __syncthreads();
        float4* sW4 = (float4*)sW;
        for (int i = tid; i < 1536; i += 128) sW4[i] = We4[dt * 1536 + i];
        __syncthreads();
#pragma unroll 4
        for (int dl = 0; dl < 128; dl++) {
            const ulonglong2* wr = (const ulonglong2*)(sW + dl * 48);  // 12 x 16B
            ull a0 = 0ull, a1 = 0ull, a2 = 0ull, a3 = 0ull;
#pragma unroll
            for (int k = 0; k < 12; k += 2) {
                ulonglong2 w0 = wr[k];
                ulonglong2 w1 = wr[k + 1];
                a0 = ffma2(ep[2 * k + 0], w0.x, a0);
                a1 = ffma2(ep[2 * k + 1], w0.y, a1);
                a2 = ffma2(ep[2 * k + 2], w1.x, a2);
                a3 = ffma2(ep[2 * k + 3], w1.y, a3);
            }
            float l0, h0, l1, h1, l2, h2, l3, h3;
            unpack2(a0, l0, h0);
            unpack2(a1, l1, h1);
            unpack2(a2, l2, h2);
            unpack2(a3, l3, h3);
            int d = dt * 128 + dl;
            float s = ((l0 + h0) + (l1 + h1)) + ((l2 + h2) + (l3 + h3)) + sB[d];
            zb[(size_t)d * LLAT] = fmaxf(s, 0.f);
        }
    }
}

// ---------------------------------------------------------------------------
// Distance GEMM + fused argmin, packed f32x2 mainloop.
// cross[n,k] = sum_d z[n,d]*cb[d,k]; score = w2[k] - 2*cross. argmin over all K.
// Block: 64 rows x 128 k per chunk (4 chunks), BK=16, 256 threads, 4x8 microtile.
// A tile stored DUPLICATED ((a,a) pairs) so am2 comes straight from LDS.128.
__global__ void k_argmin(const float* __restrict__ ze, const float* __restrict__ cb) {
    __shared__ float As2[16][128];  // 8 KB, row r duplicated at cols 2r, 2r+1
    __shared__ float Bs[16][128];   // 8 KB
    __shared__ float w2s[KB];       // 2 KB
    const int tid = threadIdx.x;  // 256
    for (int i = tid; i < KB; i += 256) w2s[i] = g_w2[i];

    const int n0 = blockIdx.x * 64;  // 512 blocks
    const int b = n0 >> 10;
    const int p0 = n0 & 1023;
    const float* zb = ze + (size_t)b * (DD * LLAT) + p0;
    const int tx = tid & 15, ty = tid >> 4;
    const int m4 = (tid & 15) << 2;  // loader: 4 source floats per thread per dd
    const int ldd = tid >> 4;        // loader dd (0..15)
    const int k8 = (tid & 15) << 3;  // B loader col

    float runv[4];
    int runi[4];
#pragma unroll
    for (int i = 0; i < 4; i++) { runv[i] = INFINITY; runi[i] = 0; }

    for (int kc = 0; kc < 4; kc++) {
        const int k0 = kc << 7;
        ull acc[4][4];
#pragma unroll
        for (int i = 0; i < 4; i++)
#pragma unroll
            for (int j = 0; j < 4; j++) acc[i][j] = 0ull;

        for (int d0 = 0; d0 < DD; d0 += 16) {
            __syncthreads();
            // A: 16 dd x 64 rows -> duplicated pairs
            {
                float4 v = *(const float4*)(zb + (size_t)(d0 + ldd) * LLAT + m4);
                float4* dst = (float4*)&As2[ldd][m4 << 1];
                dst[0] = make_float4(v.x, v.x, v.y, v.y);
                dst[1] = make_float4(v.z, v.z, v.w, v.w);
            }
            // B: 16 dd x 128 k
            {
                const float4* src = (const float4*)(cb + (size_t)(d0 + ldd) * KB + k0 + k8);
                float4* dst = (float4*)&Bs[ldd][k8];
                dst[0] = src[0];
                dst[1] = src[1];
            }
            __syncthreads();
#pragma unroll
            for (int dd = 0; dd < 16; dd++) {
                ulonglong2 a01 = *(const ulonglong2*)&As2[dd][ty << 3];
                ulonglong2 a23 = *(const ulonglong2*)&As2[dd][(ty << 3) + 4];
                ulonglong2 b01 = *(const ulonglong2*)&Bs[dd][tx << 3];
                ulonglong2 b23 = *(const ulonglong2*)&Bs[dd][(tx << 3) + 4];
                ull am[4] = {a01.x, a01.y, a23.x, a23.y};
                ull bn[4] = {b01.x, b01.y, b23.x, b23.y};
#pragma unroll
                for (int i = 0; i < 4; i++)
#pragma unroll
                    for (int j = 0; j < 4; j++) acc[i][j] = ffma2(am[i], bn[j], acc[i][j]);
            }
        }
        // Epilogue: acc[i][j] halves map to k = k0 + tx*8 + 2j (lo), +2j+1 (hi)
#pragma unroll
        for (int i = 0; i < 4; i++)
#pragma unroll
            for (int j = 0; j < 4; j++) {
                float clo, chi;
                unpack2(acc[i][j], clo, chi);
                int klo = k0 + (tx << 3) + 2 * j;
                float slo = w2s[klo] - 2.f * clo;
                float shi = w2s[klo + 1] - 2.f * chi;
                if (slo < runv[i] || (slo == runv[i] && klo < runi[i])) {
                    runv[i] = slo;
                    runi[i] = klo;
                }
                if (shi < runv[i] || (shi == runv[i] && klo + 1 < runi[i])) {
                    runv[i] = shi;
                    runi[i] = klo + 1;
                }
            }
    }

    // Reduce across the 16 tx lanes sharing each row
#pragma unroll
    for (int i = 0; i < 4; i++) {
        float v = runv[i];
        int ix = runi[i];
#pragma unroll
        for (int off = 8; off >= 1; off >>= 1) {
            float ov = __shfl_xor_sync(0xffffffffu, v, off);
            int oi = __shfl_xor_sync(0xffffffffu, ix, off);
            if (ov < v || (ov == v && oi < ix)) { v = ov; ix = oi; }
        }
        if (tx == 0) g_idx[n0 + (ty << 2) + i] = ix;
    }
}

// ---------------------------------------------------------------------------
// Gather: emb = cb[:, idx]; z_q = z_e + (emb - z_e) (straight-through forward).
__global__ void k_gather(const float* __restrict__ cb, const float* __restrict__ ze,
                         float* __restrict__ emb) {
    size_t t = (size_t)blockIdx.x * 256 + threadIdx.x;  // 4194304 threads
    size_t e = t << 2;                                  // float4 index base
    int p = (int)(e & 1023);
    int d = (int)((e >> 10) & 511);
    int bi = (int)(e >> 19);
    int n0 = (bi << 10) + p;
    int4 iv = *(const int4*)(g_idx + n0);
    const float* cbd = cb + d * KB;
    float4 q;
    q.x = cbd[iv.x];
    q.y = cbd[iv.y];
    q.z = cbd[iv.z];
    q.w = cbd[iv.w];
    float4 z = *(const float4*)(ze + e);
    float4 zo;
    zo.x = z.x + (q.x - z.x);
    zo.y = z.y + (q.y - z.y);
    zo.z = z.z + (q.z - z.z);
    zo.w = z.w + (q.w - z.w);
    *(float4*)(emb + e) = q;
    *(float4*)(g_zq + e) = zo;
}

// ---------------------------------------------------------------------------
// Decoder: out[b,c,4h+i,4w+j] = sigmoid( sum_d zq[b,d,h,w]*wdt[d][c*16+i*4+j] + bd[c] )
// Packed f32x2 inner loop: z duplicated, weight pairs straight from smem.
__global__ void k_decoder(const float* __restrict__ bd, float* __restrict__ out) {
    __shared__ float sz[64][32];
    __shared__ float sw[64][48];
    __shared__ float so[48][33];
    const int tid = threadIdx.x;  // 192
    const int blk = blockIdx.x;   // 1024 blocks
    const int b = blk >> 5, h = blk & 31;
    const float* zb = g_zq + (size_t)b * (DD * LLAT) + h * 32;
    const int w = tid & 31, g = tid >> 5;  // g in 0..5

    ull accp[4];
#pragma unroll
    for (int q = 0; q < 4; q++) accp[q] = 0ull;

    for (int d0 = 0; d0 < DD; d0 += 64) {
        __syncthreads();
        for (int idx = tid; idx < 2048; idx += 192) {
            int dd = idx >> 5, ww = idx & 31;
            sz[dd][ww] = zb[(size_t)(d0 + dd) * LLAT + ww];
        }
        for (int idx = tid; idx < 3072; idx += 192)
            ((float*)sw)[idx] = g_wdt[d0 * 48 + idx];
        __syncthreads();
#pragma unroll 16
        for (int dd = 0; dd < 64; dd++) {
            float zv = sz[dd][w];
            ull zz = pack2(zv, zv);
            ulonglong2 w01 = *(const ulonglong2*)&sw[dd][g * 8];
            ulonglong2 w23 = *(const ulonglong2*)&sw[dd][g * 8 + 4];
            accp[0] = ffma2(zz, w01.x, accp[0]);
            accp[1] = ffma2(zz, w01.y, accp[1]);
            accp[2] = ffma2(zz, w23.x, accp[2]);
            accp[3] = ffma2(zz, w23.y, accp[3]);
        }
    }

    __syncthreads();
#pragma unroll
    for (int q = 0; q < 4; q++) {
        float lo, hi;
        unpack2(accp[q], lo, hi);
        so[g * 8 + 2 * q][w] = lo;
        so[g * 8 + 2 * q + 1][w] = hi;
    }
    __syncthreads();

    float* ob = out + (size_t)b * (3 * 16384);
    for (int idx = tid; idx < 1536; idx += 192) {
        int r = idx >> 7;    // 0..11 : c = r>>2, i = r&3
        int col = idx & 127; // 4w + j
        int c = r >> 2, i = r & 3;
        int o = c * 16 + i * 4 + (col & 3);
        float v = so[o][col >> 2] + bd[c];
        ob[c * 16384 + (4 * h + i) * 128 + col] = 1.f / (1.f + expf(-v));
    }
}

// ---------------------------------------------------------------------------
extern "C" void kernel_launch(void* const* d_in, const int* in_sizes, int n_in,
                              void* d_out, int out_size) {
    const float* x = (const float*)d_in[0];
    const float* We = (const float*)d_in[1];
    const float* be = (const float*)d_in[2];
    const float* Wd = (const float*)d_in[3];
    const float* bd = (const float*)d_in[4];
    const float* cb = (const float*)d_in[5];

    float* out = (float*)d_out;
    float* recon = out;
    float* ze = out + RECON_ELEMS;
    float* emb = out + RECON_ELEMS + ZE_ELEMS;

    k_prep_w2<<<1, 512>>>(cb);
    k_prep_wdt<<<96, 256>>>(Wd);
    k_encoder<<<256, 128>>>(x, We, be, ze);
    k_argmin<<<512, 256>>>(ze, cb);
    k_gather<<<16384, 256>>>(cb, ze, emb);
    k_decoder<<<1024, 192>>>(bd, recon);
}

// round 8
// speedup vs baseline: 1.7184x; 1.7184x over previous
#include <cuda_runtime.h>
#include <math.h>
#include <stdint.h>

// Problem constants
#define BB 32
#define DD 512
#define KB 512            // codebook size
#define LLAT 1024         // latent positions per image (32*32)
#define NTOT (BB * LLAT)  // 32768 rows

// d_out layout: [recon (32*3*128*128)] [z_e (32*512*1024)] [emb (32*512*1024)]
#define RECON_ELEMS (32 * 3 * 128 * 128)
#define ZE_ELEMS (BB * DD * LLAT)

// Scratch (device globals: allocation-free)
__device__ float g_zq[(size_t)NTOT * DD];  // z_q in NCHW layout (b,d,p)
__device__ int g_idx[NTOT];
__device__ float g_w2[KB];
__device__ float g_wdt[DD * 48];  // decoder weights, flipped, [d][c*16+i*4+j]

typedef unsigned long long ull;

// Packed fp32x2 FMA: two IEEE fp32 FMAs per instruction (bit-exact per lane).
__device__ __forceinline__ ull ffma2(ull a, ull b, ull c) {
    ull d;
    asm("fma.rn.f32x2 %0, %1, %2, %3;" : "=l"(d) : "l"(a), "l"(b), "l"(c));
    return d;
}
__device__ __forceinline__ ull pack2(float lo, float hi) {
    ull d;
    asm("mov.b64 %0, {%1, %2};" : "=l"(d) : "f"(lo), "f"(hi));
    return d;
}
__device__ __forceinline__ void unpack2(ull v, float& lo, float& hi) {
    asm("mov.b64 {%0, %1}, %2;" : "=f"(lo), "=f"(hi) : "l"(v));
}

// ---------------------------------------------------------------------------
// Prep: codebook column norms
__global__ void k_prep_w2(const float* __restrict__ cb) {
    int k = threadIdx.x;  // 512 threads
    float s = 0.f;
    for (int d = 0; d < DD; d++) {
        float v = cb[d * KB + k];
        s += v * v;
    }
    g_w2[k] = s;
}

// Prep: decoder weight transpose WITH spatial flip.
// jax conv_transpose (transpose_kernel=False, VALID, k=s=4):
//   out[b,c,4h+i,4w+j] = sum_d zq[b,d,h,w] * Wd[c,d,3-i,3-j] + bd[c]
__global__ void k_prep_wdt(const float* __restrict__ Wd) {
    int t = blockIdx.x * 256 + threadIdx.x;  // 24576 total
    int d = t / 48, m = t % 48;
    int c = m >> 4, ij = m & 15;
    int i = ij >> 2, j = ij & 3;
    g_wdt[t] = Wd[c * (DD * 16) + d * 16 + (3 - i) * 4 + (3 - j)];
}

// ---------------------------------------------------------------------------
// Encoder: z_e[b,d,p] = relu( sum_{c,i,j} x[b,c,4h+i,4w+j]*We[d,c,i,j] + be[d] )
__global__ void k_encoder(const float* __restrict__ x, const float* __restrict__ We,
                          const float* __restrict__ be, float* __restrict__ ze) {
    __shared__ float sW[128 * 48];  // 24 KB
    __shared__ float sB[DD];
    const int tid = threadIdx.x;  // 128
    const int blk = blockIdx.x;   // 256 blocks
    const int b = blk >> 3;
    const int p = ((blk & 7) << 7) + tid;  // 0..1023
    const int h = p >> 5, w = p & 31;

    for (int i = tid; i < DD; i += 128) sB[i] = be[i];

    float patch[48];
    const float* xb = x + (size_t)b * (3 * 128 * 128);
#pragma unroll
    for (int c = 0; c < 3; c++)
#pragma unroll
        for (int i = 0; i < 4; i++) {
            float4 v = *(const float4*)(xb + c * 16384 + (4 * h + i) * 128 + 4 * w);
            patch[c * 16 + i * 4 + 0] = v.x;
            patch[c * 16 + i * 4 + 1] = v.y;
            patch[c * 16 + i * 4 + 2] = v.z;
            patch[c * 16 + i * 4 + 3] = v.w;
        }

    float* zb = ze + (size_t)b * (DD * LLAT) + p;
    const float4* We4 = (const float4*)We;
    for (int dt = 0; dt < 4; dt++) {
        __syncthreads();
        float4* sW4 = (float4*)sW;
        for (int i = tid; i < 1536; i += 128) sW4[i] = We4[dt * 1536 + i];
        __syncthreads();
#pragma unroll 4
        for (int dl = 0; dl < 128; dl++) {
            const float* wr = sW + dl * 48;
            float a0 = 0.f, a1 = 0.f, a2 = 0.f, a3 = 0.f;
#pragma unroll
            for (int k = 0; k < 48; k += 4) {
                a0 += patch[k + 0] * wr[k + 0];
                a1 += patch[k + 1] * wr[k + 1];
                a2 += patch[k + 2] * wr[k + 2];
                a3 += patch[k + 3] * wr[k + 3];
            }
            int d = dt * 128 + dl;
            float s = (a0 + a1) + (a2 + a3) + sB[d];
            zb[(size_t)d * LLAT] = fmaxf(s, 0.f);
        }
    }
}

// ---------------------------------------------------------------------------
// Distance GEMM + fused argmin, FFMA2 + 8x8 microtile, register-prefetch
// double buffering (single smem buffer, no cp.async).
// score[n,k] = w2[k] - 2 * sum_d z[n,d]*cb[d,k]; argmin over all 512 k.
// Block: 128 rows x 128-k chunk (4 chunks looped), BK=16, 256 threads.
// Per thread: 8 rows x 8 cols (acc as 8x4 f32x2 pairs). 1 B/MAC smem traffic.
__global__ void __launch_bounds__(256, 2)
k_argmin(const float* __restrict__ ze, const float* __restrict__ cb) {
    __shared__ float As[16][128];  // [dd][row]  8 KB
    __shared__ float Bs[16][128];  // [dd][col]  8 KB
    __shared__ float w2s[KB];      // 2 KB
    const int tid = threadIdx.x;  // 256
    for (int i = tid; i < KB; i += 256) w2s[i] = g_w2[i];

    const int n0 = blockIdx.x * 128;  // 256 blocks, no image straddle (1024%128==0)
    const int b = n0 >> 10;
    const int p0 = n0 & 1023;
    const float* zb = ze + (size_t)b * (DD * LLAT) + p0;

    const int tx = tid & 15;  // col group: cols tx*8..tx*8+7
    const int ty = tid >> 4;  // row group: rows ty*8..ty*8+7

    // Loader mapping: each thread moves 4x16B per tile (2 A + 2 B rows).
    const int la_d = tid >> 5;         // 0..7
    const int la_m = (tid & 31) << 2;  // 0..124 (floats)

    // Register prefetch staging (next tile while current computes).
    float4 ra0, ra1, rb0, rb1;
    // tile index s: kc = s>>5, d0 = (s&31)*16
    auto fetch = [&](int s) {
        const int kc = s >> 5;
        const int d0 = (s & 31) << 4;
        const float* ap = zb + (size_t)(d0 + la_d) * LLAT + la_m;
        const float* bp = cb + (size_t)(d0 + la_d) * KB + (kc << 7) + la_m;
        ra0 = *(const float4*)ap;
        ra1 = *(const float4*)(ap + 8 * LLAT);
        rb0 = *(const float4*)bp;
        rb1 = *(const float4*)(bp + 8 * KB);
    };

    float runv[8];
    int runi[8];
#pragma unroll
    for (int i = 0; i < 8; i++) { runv[i] = INFINITY; runi[i] = 0; }

    fetch(0);

    for (int kc = 0; kc < 4; kc++) {
        const int k0 = kc << 7;
        ull acc[8][4];
#pragma unroll
        for (int i = 0; i < 8; i++)
#pragma unroll
            for (int j = 0; j < 4; j++) acc[i][j] = 0ull;

        for (int d0 = 0; d0 < DD; d0 += 16) {
            __syncthreads();  // prior compute done -> safe to overwrite tile
            *(float4*)&As[la_d][la_m] = ra0;
            *(float4*)&As[la_d + 8][la_m] = ra1;
            *(float4*)&Bs[la_d][la_m] = rb0;
            *(float4*)&Bs[la_d + 8][la_m] = rb1;
            __syncthreads();  // tile visible to all

            const int s = (kc << 5) + (d0 >> 4) + 1;  // next tile
            if (s < 128) fetch(s);  // overlap global latency with compute below

#pragma unroll
            for (int dd = 0; dd < 16; dd++) {
                float4 a0 = *(const float4*)&As[dd][ty << 3];
                float4 a1 = *(const float4*)&As[dd][(ty << 3) + 4];
                ulonglong2 b01 = *(const ulonglong2*)&Bs[dd][tx << 3];
                ulonglong2 b23 = *(const ulonglong2*)&Bs[dd][(tx << 3) + 4];
                ull bn[4] = {b01.x, b01.y, b23.x, b23.y};
                ull ap[8];
                ap[0] = pack2(a0.x, a0.x);
                ap[1] = pack2(a0.y, a0.y);
                ap[2] = pack2(a0.z, a0.z);
                ap[3] = pack2(a0.w, a0.w);
                ap[4] = pack2(a1.x, a1.x);
                ap[5] = pack2(a1.y, a1.y);
                ap[6] = pack2(a1.z, a1.z);
                ap[7] = pack2(a1.w, a1.w);
#pragma unroll
                for (int i = 0; i < 8; i++)
#pragma unroll
                    for (int j = 0; j < 4; j++) acc[i][j] = ffma2(ap[i], bn[j], acc[i][j]);
            }
        }

        // Epilogue: acc[i][j] -> cols k0+tx*8+2j (lo), +2j+1 (hi); row ty*8+i
#pragma unroll
        for (int i = 0; i < 8; i++)
#pragma unroll
            for (int j = 0; j < 4; j++) {
                float clo, chi;
                unpack2(acc[i][j], clo, chi);
                int klo = k0 + (tx << 3) + 2 * j;
                float slo = w2s[klo] - 2.f * clo;
                float shi = w2s[klo + 1] - 2.f * chi;
                if (slo < runv[i] || (slo == runv[i] && klo < runi[i])) {
                    runv[i] = slo;
                    runi[i] = klo;
                }
                if (shi < runv[i] || (shi == runv[i] && klo + 1 < runi[i])) {
                    runv[i] = shi;
                    runi[i] = klo + 1;
                }
            }
    }

    // Reduce across the 16 tx lanes sharing each row (lanes 0-15 / 16-31 of warp)
#pragma unroll
    for (int i = 0; i < 8; i++) {
        float v = runv[i];
        int ix = runi[i];
#pragma unroll
        for (int off = 8; off >= 1; off >>= 1) {
            float ov = __shfl_xor_sync(0xffffffffu, v, off);
            int oi = __shfl_xor_sync(0xffffffffu, ix, off);
            if (ov < v || (ov == v && oi < ix)) { v = ov; ix = oi; }
        }
        if (tx == 0) g_idx[n0 + (ty << 3) + i] = ix;
    }
}

// ---------------------------------------------------------------------------
// Gather: emb = cb[:, idx]; z_q = z_e + (emb - z_e) (straight-through forward).
__global__ void k_gather(const float* __restrict__ cb, const float* __restrict__ ze,
                         float* __restrict__ emb) {
    size_t t = (size_t)blockIdx.x * 256 + threadIdx.x;  // 4194304 threads
    size_t e = t << 2;                                  // float4 index base
    int p = (int)(e & 1023);
    int d = (int)((e >> 10) & 511);
    int bi = (int)(e >> 19);
    int n0 = (bi << 10) + p;
    int4 iv = *(const int4*)(g_idx + n0);
    const float* cbd = cb + d * KB;
    float4 q;
    q.x = cbd[iv.x];
    q.y = cbd[iv.y];
    q.z = cbd[iv.z];
    q.w = cbd[iv.w];
    float4 z = *(const float4*)(ze + e);
    float4 zo;
    zo.x = z.x + (q.x - z.x);
    zo.y = z.y + (q.y - z.y);
    zo.z = z.z + (q.z - z.z);
    zo.w = z.w + (q.w - z.w);
    *(float4*)(emb + e) = q;
    *(float4*)(g_zq + e) = zo;
}

// ---------------------------------------------------------------------------
// Decoder: out[b,c,4h+i,4w+j] = sigmoid( sum_d zq[b,d,h,w]*wdt[d][c*16+i*4+j] + bd[c] )
__global__ void k_decoder(const float* __restrict__ bd, float* __restrict__ out) {
    __shared__ float sz[64][32];
    __shared__ float sw[64][48];
    __shared__ float so[48][33];
    const int tid = threadIdx.x;  // 192
    const int blk = blockIdx.x;   // 1024 blocks
    const int b = blk >> 5, h = blk & 31;
    const float* zb = g_zq + (size_t)b * (DD * LLAT) + h * 32;
    const int w = tid & 31, g = tid >> 5;  // g in 0..5

    float acc[8];
#pragma unroll
    for (int q = 0; q < 8; q++) acc[q] = 0.f;

    for (int d0 = 0; d0 < DD; d0 += 64) {
        __syncthreads();
        for (int idx = tid; idx < 2048; idx += 192) {
            int dd = idx >> 5, ww = idx & 31;
            sz[dd][ww] = zb[(size_t)(d0 + dd) * LLAT + ww];
        }
        for (int idx = tid; idx < 3072; idx += 192)
            ((float*)sw)[idx] = g_wdt[d0 * 48 + idx];
        __syncthreads();
#pragma unroll 16
        for (int dd = 0; dd < 64; dd++) {
            float zv = sz[dd][w];
            float4 w0 = *(float4*)&sw[dd][g * 8];
            float4 w1 = *(float4*)&sw[dd][g * 8 + 4];
            acc[0] += zv * w0.x;
            acc[1] += zv * w0.y;
            acc[2] += zv * w0.z;
            acc[3] += zv * w0.w;
            acc[4] += zv * w1.x;
            acc[5] += zv * w1.y;
            acc[6] += zv * w1.z;
            acc[7] += zv * w1.w;
        }
    }

    __syncthreads();
#pragma unroll
    for (int q = 0; q < 8; q++) so[g * 8 + q][w] = acc[q];
    __syncthreads();

    float* ob = out + (size_t)b * (3 * 16384);
    for (int idx = tid; idx < 1536; idx += 192) {
        int r = idx >> 7;    // 0..11 : c = r>>2, i = r&3
        int col = idx & 127; // 4w + j
        int c = r >> 2, i = r & 3;
        int o = c * 16 + i * 4 + (col & 3);
        float v = so[o][col >> 2] + bd[c];
        ob[c * 16384 + (4 * h + i) * 128 + col] = 1.f / (1.f + expf(-v));
    }
}

// ---------------------------------------------------------------------------
extern "C" void kernel_launch(void* const* d_in, const int* in_sizes, int n_in,
                              void* d_out, int out_size) {
    const float* x = (const float*)d_in[0];
    const float* We = (const float*)d_in[1];
    const float* be = (const float*)d_in[2];
    const float* Wd = (const float*)d_in[3];
    const float* bd = (const float*)d_in[4];
    const float* cb = (const float*)d_in[5];

    float* out = (float*)d_out;
    float* recon = out;
    float* ze = out + RECON_ELEMS;
    float* emb = out + RECON_ELEMS + ZE_ELEMS;

    k_prep_w2<<<1, 512>>>(cb);
    k_prep_wdt<<<96, 256>>>(Wd);
    k_encoder<<<256, 128>>>(x, We, be, ze);
    k_argmin<<<256, 256>>>(ze, cb);
    k_gather<<<16384, 256>>>(cb, ze, emb);
    k_decoder<<<1024, 192>>>(bd, recon);
}

// round 10
// speedup vs baseline: 1.8412x; 1.0714x over previous
#include <cuda_runtime.h>
#include <math.h>
#include <stdint.h>

// Problem constants
#define BB 32
#define DD 512
#define KB 512            // codebook size
#define LLAT 1024         // latent positions per image (32*32)
#define NTOT (BB * LLAT)  // 32768 rows

// d_out layout: [recon (32*3*128*128)] [z_e (32*512*1024)] [emb (32*512*1024)]
#define RECON_ELEMS (32 * 3 * 128 * 128)
#define ZE_ELEMS (BB * DD * LLAT)

// Scratch (device globals: allocation-free)
__device__ float g_zq[(size_t)NTOT * DD];  // z_q in NCHW layout (b,d,p)
__device__ int g_idx[NTOT];
__device__ float g_w2[KB];
__device__ float g_wdt[DD * 48];  // decoder weights, flipped, [d][c*16+i*4+j]

typedef unsigned long long ull;

// Packed fp32x2 FMA: two IEEE fp32 FMAs per instruction (bit-exact per lane).
__device__ __forceinline__ ull ffma2(ull a, ull b, ull c) {
    ull d;
    asm("fma.rn.f32x2 %0, %1, %2, %3;" : "=l"(d) : "l"(a), "l"(b), "l"(c));
    return d;
}
__device__ __forceinline__ ull pack2(float lo, float hi) {
    ull d;
    asm("mov.b64 %0, {%1, %2};" : "=l"(d) : "f"(lo), "f"(hi));
    return d;
}
__device__ __forceinline__ void unpack2(ull v, float& lo, float& hi) {
    asm("mov.b64 {%0, %1}, %2;" : "=f"(lo), "=f"(hi) : "l"(v));
}

// ---------------------------------------------------------------------------
// Prep: codebook column norms
__global__ void k_prep_w2(const float* __restrict__ cb) {
    int k = threadIdx.x;  // 512 threads
    float s = 0.f;
    for (int d = 0; d < DD; d++) {
        float v = cb[d * KB + k];
        s += v * v;
    }
    g_w2[k] = s;
}

// Prep: decoder weight transpose WITH spatial flip.
// jax conv_transpose (transpose_kernel=False, VALID, k=s=4):
//   out[b,c,4h+i,4w+j] = sum_d zq[b,d,h,w] * Wd[c,d,3-i,3-j] + bd[c]
__global__ void k_prep_wdt(const float* __restrict__ Wd) {
    int t = blockIdx.x * 256 + threadIdx.x;  // 24576 total
    int d = t / 48, m = t % 48;
    int c = m >> 4, ij = m & 15;
    int i = ij >> 2, j = ij & 3;
    g_wdt[t] = Wd[c * (DD * 16) + d * 16 + (3 - i) * 4 + (3 - j)];
}

// ---------------------------------------------------------------------------
// Encoder: z_e[b,d,p] = relu( sum_{c,i,j} x[b,c,4h+i,4w+j]*We[d,c,i,j] + be[d] )
// Grid 1024 = (b:32, dt:4, pg:8); 128 threads = one position each, 128 d's each.
// 4x the threads of the old version -> latency hidden, not throughput-bound.
__global__ void k_encoder(const float* __restrict__ x, const float* __restrict__ We,
                          const float* __restrict__ be, float* __restrict__ ze) {
    __shared__ float sW[128 * 48];  // 24 KB (one 128-d chunk of We)
    __shared__ float sB[128];
    const int tid = threadIdx.x;  // 128
    const int blk = blockIdx.x;   // 1024 blocks
    const int b = blk >> 5;
    const int dt = (blk >> 3) & 3;  // d chunk
    const int p = ((blk & 7) << 7) + tid;
    const int h = p >> 5, w = p & 31;

    if (tid < 128) sB[tid] = be[dt * 128 + tid];
    {
        const float4* We4 = (const float4*)We;
        float4* sW4 = (float4*)sW;
        for (int i = tid; i < 1536; i += 128) sW4[i] = We4[dt * 1536 + i];
    }

    float patch[48];
    const float* xb = x + (size_t)b * (3 * 128 * 128);
#pragma unroll
    for (int c = 0; c < 3; c++)
#pragma unroll
        for (int i = 0; i < 4; i++) {
            float4 v = *(const float4*)(xb + c * 16384 + (4 * h + i) * 128 + 4 * w);
            patch[c * 16 + i * 4 + 0] = v.x;
            patch[c * 16 + i * 4 + 1] = v.y;
            patch[c * 16 + i * 4 + 2] = v.z;
            patch[c * 16 + i * 4 + 3] = v.w;
        }
    __syncthreads();

    float* zb = ze + (size_t)b * (DD * LLAT) + (size_t)(dt * 128) * LLAT + p;
#pragma unroll 4
    for (int dl = 0; dl < 128; dl++) {
        const float* wr = sW + dl * 48;
        float a0 = 0.f, a1 = 0.f, a2 = 0.f, a3 = 0.f;
#pragma unroll
        for (int k = 0; k < 48; k += 4) {
            a0 += patch[k + 0] * wr[k + 0];
            a1 += patch[k + 1] * wr[k + 1];
            a2 += patch[k + 2] * wr[k + 2];
            a3 += patch[k + 3] * wr[k + 3];
        }
        float s = (a0 + a1) + (a2 + a3) + sB[dl];
        zb[(size_t)dl * LLAT] = fmaxf(s, 0.f);
    }
}

// ---------------------------------------------------------------------------
// Distance GEMM + fused argmin: FFMA2 8x8 microtile, double-buffered smem with
// register prefetch, ONE __syncthreads per BK-step.
// score[n,k] = w2[k] - 2 * sum_d z[n,d]*cb[d,k]; argmin over all 512 k.
// 128 tiles stream linearly (tile s: kc = s>>5, d0 = (s&31)*16).
__global__ void __launch_bounds__(256, 2)
k_argmin(const float* __restrict__ ze, const float* __restrict__ cb) {
    __shared__ float As[2][16][128];  // 16 KB
    __shared__ float Bs[2][16][128];  // 16 KB
    __shared__ float w2s[KB];         // 2 KB
    const int tid = threadIdx.x;  // 256
    for (int i = tid; i < KB; i += 256) w2s[i] = g_w2[i];

    const int n0 = blockIdx.x * 128;  // 256 blocks
    const int b = n0 >> 10;
    const int p0 = n0 & 1023;
    const float* zb = ze + (size_t)b * (DD * LLAT) + p0;

    const int tx = tid & 15;  // cols tx*8..tx*8+7
    const int ty = tid >> 4;  // rows ty*8..ty*8+7

    const int la_d = tid >> 5;         // 0..7
    const int la_m = (tid & 31) << 2;  // 0..124

    float4 ra0, ra1, rb0, rb1;  // staged next tile
    auto fetch = [&](int s) {
        const int kc = s >> 5;
        const int d0 = (s & 31) << 4;
        const float* ap = zb + (size_t)(d0 + la_d) * LLAT + la_m;
        const float* bp = cb + (size_t)(d0 + la_d) * KB + (kc << 7) + la_m;
        ra0 = *(const float4*)ap;
        ra1 = *(const float4*)(ap + 8 * LLAT);
        rb0 = *(const float4*)bp;
        rb1 = *(const float4*)(bp + 8 * KB);
    };
    auto store_tile = [&](int buf) {
        *(float4*)&As[buf][la_d][la_m] = ra0;
        *(float4*)&As[buf][la_d + 8][la_m] = ra1;
        *(float4*)&Bs[buf][la_d][la_m] = rb0;
        *(float4*)&Bs[buf][la_d + 8][la_m] = rb1;
    };

    float runv[8];
    int runi[8];
#pragma unroll
    for (int i = 0; i < 8; i++) { runv[i] = INFINITY; runi[i] = 0; }

    // Prologue: tile 0 in smem buf0, tile 1 staged in regs.
    fetch(0);
    store_tile(0);
    fetch(1);
    __syncthreads();

    int t = 0;  // global tile counter
    for (int kc = 0; kc < 4; kc++) {
        const int k0 = kc << 7;
        ull acc[8][4];
#pragma unroll
        for (int i = 0; i < 8; i++)
#pragma unroll
            for (int j = 0; j < 4; j++) acc[i][j] = 0ull;

        for (int step = 0; step < 32; step++, t++) {
            const int p = t & 1;
            // Store staged tile t+1 -> other buffer (safe: last read of that
            // buffer was iter t-1's compute, sealed by iter t-1's barrier).
            if (t + 1 < 128) store_tile(p ^ 1);
            if (t + 2 < 128) fetch(t + 2);  // LDG overlaps compute below

            const float(*Ac)[128] = As[p];
            const float(*Bc)[128] = Bs[p];
#pragma unroll
            for (int dd = 0; dd < 16; dd++) {
                float4 a0 = *(const float4*)&Ac[dd][ty << 3];
                float4 a1 = *(const float4*)&Ac[dd][(ty << 3) + 4];
                ulonglong2 b01 = *(const ulonglong2*)&Bc[dd][tx << 3];
                ulonglong2 b23 = *(const ulonglong2*)&Bc[dd][(tx << 3) + 4];
                ull bn[4] = {b01.x, b01.y, b23.x, b23.y};
                ull ap[8];
                ap[0] = pack2(a0.x, a0.x);
                ap[1] = pack2(a0.y, a0.y);
                ap[2] = pack2(a0.z, a0.z);
                ap[3] = pack2(a0.w, a0.w);
                ap[4] = pack2(a1.x, a1.x);
                ap[5] = pack2(a1.y, a1.y);
                ap[6] = pack2(a1.z, a1.z);
                ap[7] = pack2(a1.w, a1.w);
#pragma unroll
                for (int i = 0; i < 8; i++)
#pragma unroll
                    for (int j = 0; j < 4; j++) acc[i][j] = ffma2(ap[i], bn[j], acc[i][j]);
            }
            __syncthreads();  // single barrier per BK-step
        }

        // Epilogue: acc[i][j] -> cols k0+tx*8+2j (lo), +2j+1 (hi); row ty*8+i
#pragma unroll
        for (int i = 0; i < 8; i++)
#pragma unroll
            for (int j = 0; j < 4; j++) {
                float clo, chi;
                unpack2(acc[i][j], clo, chi);
                int klo = k0 + (tx << 3) + 2 * j;
                float slo = w2s[klo] - 2.f * clo;
                float shi = w2s[klo + 1] - 2.f * chi;
                if (slo < runv[i] || (slo == runv[i] && klo < runi[i])) {
                    runv[i] = slo;
                    runi[i] = klo;
                }
                if (shi < runv[i] || (shi == runv[i] && klo + 1 < runi[i])) {
                    runv[i] = shi;
                    runi[i] = klo + 1;
                }
            }
    }

    // Reduce across the 16 tx lanes sharing each row
#pragma unroll
    for (int i = 0; i < 8; i++) {
        float v = runv[i];
        int ix = runi[i];
#pragma unroll
        for (int off = 8; off >= 1; off >>= 1) {
            float ov = __shfl_xor_sync(0xffffffffu, v, off);
            int oi = __shfl_xor_sync(0xffffffffu, ix, off);
            if (ov < v || (ov == v && oi < ix)) { v = ov; ix = oi; }
        }
        if (tx == 0) g_idx[n0 + (ty << 3) + i] = ix;
    }
}

// ---------------------------------------------------------------------------
// Gather: emb = cb[:, idx]; z_q = z_e + (emb - z_e) (straight-through forward).
__global__ void k_gather(const float* __restrict__ cb, const float* __restrict__ ze,
                         float* __restrict__ emb) {
    size_t t = (size_t)blockIdx.x * 256 + threadIdx.x;  // 4194304 threads
    size_t e = t << 2;                                  // float4 index base
    int p = (int)(e & 1023);
    int d = (int)((e >> 10) & 511);
    int bi = (int)(e >> 19);
    int n0 = (bi << 10) + p;
    int4 iv = *(const int4*)(g_idx + n0);
    const float* cbd = cb + d * KB;
    float4 q;
    q.x = cbd[iv.x];
    q.y = cbd[iv.y];
    q.z = cbd[iv.z];
    q.w = cbd[iv.w];
    float4 z = *(const float4*)(ze + e);
    float4 zo;
    zo.x = z.x + (q.x - z.x);
    zo.y = z.y + (q.y - z.y);
    zo.z = z.z + (q.z - z.z);
    zo.w = z.w + (q.w - z.w);
    *(float4*)(emb + e) = q;
    *(float4*)(g_zq + e) = zo;
}

// ---------------------------------------------------------------------------
// Decoder: out[b,c,4h+i,4w+j] = sigmoid( sum_d zq[b,d,h,w]*wdt[d][c*16+i*4+j] + bd[c] )
// FFMA2 inner loop (sw reads are warp-broadcast; sz 1 wavefront).
__global__ void k_decoder(const float* __restrict__ bd, float* __restrict__ out) {
    __shared__ float sz[64][32];
    __shared__ float sw[64][48];
    __shared__ float so[48][33];
    const int tid = threadIdx.x;  // 192
    const int blk = blockIdx.x;   // 1024 blocks
    const int b = blk >> 5, h = blk & 31;
    const float* zb = g_zq + (size_t)b * (DD * LLAT) + h * 32;
    const int w = tid & 31, g = tid >> 5;  // g in 0..5

    ull accp[4];
#pragma unroll
    for (int q = 0; q < 4; q++) accp[q] = 0ull;

    for (int d0 = 0; d0 < DD; d0 += 64) {
        __syncthreads();
        for (int idx = tid; idx < 2048; idx += 192) {
            int dd = idx >> 5, ww = idx & 31;
            sz[dd][ww] = zb[(size_t)(d0 + dd) * LLAT + ww];
        }
        for (int idx = tid; idx < 3072; idx += 192)
            ((float*)sw)[idx] = g_wdt[d0 * 48 + idx];
        __syncthreads();
#pragma unroll 16
        for (int dd = 0; dd < 64; dd++) {
            float zv = sz[dd][w];
            ull zz = pack2(zv, zv);
            ulonglong2 w01 = *(const ulonglong2*)&sw[dd][g * 8];
            ulonglong2 w23 = *(const ulonglong2*)&sw[dd][g * 8 + 4];
            accp[0] = ffma2(zz, w01.x, accp[0]);
            accp[1] = ffma2(zz, w01.y, accp[1]);
            accp[2] = ffma2(zz, w23.x, accp[2]);
            accp[3] = ffma2(zz, w23.y, accp[3]);
        }
    }

    __syncthreads();
#pragma unroll
    for (int q = 0; q < 4; q++) {
        float lo, hi;
        unpack2(accp[q], lo, hi);
        so[g * 8 + 2 * q][w] = lo;
        so[g * 8 + 2 * q + 1][w] = hi;
    }
    __syncthreads();

    float* ob = out + (size_t)b * (3 * 16384);
    for (int idx = tid; idx < 1536; idx += 192) {
        int r = idx >> 7;    // 0..11 : c = r>>2, i = r&3
        int col = idx & 127; // 4w + j
        int c = r >> 2, i = r & 3;
        int o = c * 16 + i * 4 + (col & 3);
        float v = so[o][col >> 2] + bd[c];
        ob[c * 16384 + (4 * h + i) * 128 + col] = 1.f / (1.f + expf(-v));
    }
}

// ---------------------------------------------------------------------------
extern "C" void kernel_launch(void* const* d_in, const int* in_sizes, int n_in,
                              void* d_out, int out_size) {
    const float* x = (const float*)d_in[0];
    const float* We = (const float*)d_in[1];
    const float* be = (const float*)d_in[2];
    const float* Wd = (const float*)d_in[3];
    const float* bd = (const float*)d_in[4];
    const float* cb = (const float*)d_in[5];

    float* out = (float*)d_out;
    float* recon = out;
    float* ze = out + RECON_ELEMS;
    float* emb = out + RECON_ELEMS + ZE_ELEMS;

    k_prep_w2<<<1, 512>>>(cb);
    k_prep_wdt<<<96, 256>>>(Wd);
    k_encoder<<<1024, 128>>>(x, We, be, ze);
    k_argmin<<<256, 256>>>(ze, cb);
    k_gather<<<16384, 256>>>(cb, ze, emb);
    k_decoder<<<1024, 192>>>(bd, recon);
}